// round 10
// baseline (speedup 1.0000x reference)
#include <cuda_runtime.h>
#include <cuda_fp16.h>
#include <math.h>

#define N_NODES 30000
#define E_EDGES 480000
#define VDIM    512
#define HID     32

#define SCAN_BLK 512
#define NBLKS ((N_NODES + SCAN_BLK - 1) / SCAN_BLK)   // 59

// k_A interleaved roles: groups of 11 blocks = 10 vnorm + 1 aux
#define KA_GRID  4125      // 375 groups
#define HIST_BLKS 256
#define BN_BLKS   118
// k_B interleaved roles: groups of 17 = 16 fill + 1 mlp
#define FILL_BLKS 1875     // one edge per thread (1875*256 = 480000)
#define MLP_BLKS  118
#define KB_GRID   (118 * 17)   // 2006

// ---- scratch (__device__ globals; no allocation allowed) ----
__device__ __half g_vh[N_NODES * VDIM];    // normalized visual, fp16 (30.7 MB)
__device__ float  g_p[N_NODES];
__device__ int    g_cnt[N_NODES];
__device__ int    g_rank[E_EDGES];         // per-edge rank within its dst row
__device__ int    g_rowstart[N_NODES + 1];
__device__ int    g_csr[E_EDGES];
__device__ int    g_bsum[NBLKS];
__device__ int    g_arrive;
__device__ float  g_sum[HID];
__device__ float  g_sumsq[HID];
__device__ float  g_scale[HID];
__device__ float  g_shift[HID];
__device__ float  g_u[HID];
__device__ float  g_c;

// ---------------------------------------------------------------------------
__global__ void k_zero() {
    int i = blockIdx.x * blockDim.x + threadIdx.x;
    int stride = gridDim.x * blockDim.x;
    for (int j = i; j < N_NODES; j += stride) g_cnt[j] = 0;
    if (i < HID) { g_sum[i] = 0.f; g_sumsq[i] = 0.f; }
    if (i == HID) g_arrive = 0;
}

// ---------------------------------------------------------------------------
// K_A: interleaved  vnorm | hist(+rank) | bnstats
// ---------------------------------------------------------------------------
__global__ void k_A(const float* __restrict__ visual,
                    const int* __restrict__ ei,
                    const float* __restrict__ x,
                    const float* __restrict__ w1,
                    const float* __restrict__ b1) {
    int b = blockIdx.x;
    int r = b % 11, q = b / 11;
    if (r < 10) {
        // ---- vnorm: warp per node ----
        int vb   = q * 10 + r;
        int gw   = (vb * blockDim.x + threadIdx.x) >> 5;
        int lane = threadIdx.x & 31;
        if (gw >= N_NODES) return;
        const float4* v = (const float4*)(visual + (size_t)gw * VDIM);
        float4 f[4];
        float s = 0.f;
#pragma unroll
        for (int i = 0; i < 4; i++) {
            f[i] = v[i * 32 + lane];
            s = fmaf(f[i].x, f[i].x, s); s = fmaf(f[i].y, f[i].y, s);
            s = fmaf(f[i].z, f[i].z, s); s = fmaf(f[i].w, f[i].w, s);
        }
#pragma unroll
        for (int off = 16; off > 0; off >>= 1) s += __shfl_xor_sync(0xffffffffu, s, off);
        float rn = 1.0f / fmaxf(sqrtf(s), 1e-8f);
        __half2* out = (__half2*)(g_vh + (size_t)gw * VDIM);
#pragma unroll
        for (int i = 0; i < 4; i++) {
            __half2 h0 = __floats2half2_rn(f[i].x * rn, f[i].y * rn);
            __half2 h1 = __floats2half2_rn(f[i].z * rn, f[i].w * rn);
            uint2 pk;
            pk.x = *(unsigned int*)&h0;
            pk.y = *(unsigned int*)&h1;
            *(uint2*)(out + i * 64 + lane * 2) = pk;
        }
    } else if (q < HIST_BLKS) {
        // ---- hist: in-degree + per-edge rank ----
        int i = q * blockDim.x + threadIdx.x;
        int stride = HIST_BLKS * blockDim.x;
        for (int e = i; e < E_EDGES; e += stride) {
            int dst = ei[E_EDGES + e];
            int rk = atomicAdd(&g_cnt[dst], 1);
            g_rank[e] = rk;
        }
    } else if (q < HIST_BLKS + BN_BLKS) {
        // ---- bnstats ----
        int n = (q - HIST_BLKS) * blockDim.x + threadIdx.x;
        int lane = threadIdx.x & 31;
        bool valid = (n < N_NODES);
        float x0 = 0.f, x1 = 0.f;
        if (valid) { x0 = x[2 * n]; x1 = x[2 * n + 1]; }
#pragma unroll
        for (int k = 0; k < HID; k++) {
            float h = valid ? fmaf(w1[2 * k], x0, fmaf(w1[2 * k + 1], x1, b1[k])) : 0.f;
            float s = h, s2 = h * h;
#pragma unroll
            for (int off = 16; off > 0; off >>= 1) {
                s  += __shfl_xor_sync(0xffffffffu, s,  off);
                s2 += __shfl_xor_sync(0xffffffffu, s2, off);
            }
            if (lane == 0) {
                atomicAdd(&g_sum[k], s);
                atomicAdd(&g_sumsq[k], s2);
            }
        }
    }
}

// ---------------------------------------------------------------------------
// K_scanprep: blocks [0,59) grid-cooperative exclusive scan; block 59 = prep.
// ---------------------------------------------------------------------------
__global__ void k_scanprep(const float* __restrict__ gamma,
                           const float* __restrict__ beta,
                           const float* __restrict__ wc,
                           const float* __restrict__ bc,
                           const float* __restrict__ wp,
                           const float* __restrict__ bp) {
    int b = blockIdx.x;
    if (b == NBLKS) {
        int k = threadIdx.x;
        if (k >= HID) return;
        const float invN = 1.0f / (float)N_NODES;
        float mu  = g_sum[k] * invN;
        float var = g_sumsq[k] * invN - mu * mu;
        float rstd = rsqrtf(var + 1e-5f);
        float sc = rstd * gamma[k];
        g_scale[k] = sc;
        g_shift[k] = beta[k] - mu * sc;
        float u = 0.f;
#pragma unroll
        for (int j = 0; j < HID; j++) u = fmaf(wp[j], wc[j * HID + k], u);
        g_u[k] = u;
        if (k == 0) {
            float c = bp[0];
#pragma unroll
            for (int j = 0; j < HID; j++) c = fmaf(wp[j], bc[j], c);
            g_c = c;
        }
        return;
    }

    __shared__ int wsum[SCAN_BLK / 32 + 1];
    __shared__ int s_boff;
    int tid = threadIdx.x, lane = tid & 31, wid = tid >> 5;
    int i = b * SCAN_BLK + tid;
    int v = (i < N_NODES) ? g_cnt[i] : 0;
    int xv = v;
#pragma unroll
    for (int off = 1; off < 32; off <<= 1) {
        int y = __shfl_up_sync(0xffffffffu, xv, off);
        if (lane >= off) xv += y;
    }
    if (lane == 31) wsum[wid] = xv;
    __syncthreads();
    if (tid == 0) {
        int run = 0;
#pragma unroll
        for (int k = 0; k < SCAN_BLK / 32; k++) { int t = wsum[k]; wsum[k] = run; run += t; }
        g_bsum[b] = run;
        __threadfence();
        atomicAdd(&g_arrive, 1);
    }
    __syncthreads();
    int local_excl = xv - v + wsum[wid];

    if (tid == 0) {
        while (*(volatile int*)&g_arrive != NBLKS) { /* spin */ }
    }
    __syncthreads();
    __threadfence();

    if (wid == 0) {
        int a0 = (lane < b) ? g_bsum[lane] : 0;
        int a1 = (lane + 32 < b) ? g_bsum[lane + 32] : 0;
        int t = a0 + a1;
#pragma unroll
        for (int off = 16; off > 0; off >>= 1) t += __shfl_xor_sync(0xffffffffu, t, off);
        if (lane == 0) s_boff = t;
    }
    __syncthreads();

    if (i < N_NODES) g_rowstart[i] = local_excl + s_boff;
    if (b == NBLKS - 1 && tid == 0) g_rowstart[N_NODES] = E_EDGES;
}

// ---------------------------------------------------------------------------
// K_B: interleaved  fill (atomic-free, one edge per thread) | mlp
// ---------------------------------------------------------------------------
__global__ void k_B(const int* __restrict__ ei,
                    const float* __restrict__ x,
                    const float* __restrict__ w1,
                    const float* __restrict__ b1,
                    const float* __restrict__ prelu_a,
                    const float* __restrict__ w2,
                    const float* __restrict__ b2) {
    __shared__ float swu[HID];
    __shared__ float ssc[HID], ssh[HID];
    __shared__ float sconst;
    int b = blockIdx.x;
    int r = b % 17, q = b / 17;
    if (r < 16) {
        int fb = q * 16 + r;
        if (fb >= FILL_BLKS) return;
        int e = fb * blockDim.x + threadIdx.x;   // one edge per thread
        int dst = ei[E_EDGES + e];
        int src = ei[e];
        int pos = __ldg(&g_rowstart[dst]) + g_rank[e];   // no atomics
        g_csr[pos] = src;
    } else {
        if (threadIdx.x < HID) {
            int k = threadIdx.x;
            float wu = 0.f;
#pragma unroll
            for (int j = 0; j < HID; j++) wu = fmaf(g_u[j], w2[j * HID + k], wu);
            swu[k] = wu;
            ssc[k] = g_scale[k];
            ssh[k] = g_shift[k];
            if (k == 0) {
                float c2 = 0.f;
#pragma unroll
                for (int j = 0; j < HID; j++) c2 = fmaf(g_u[j], b2[j], c2);
                sconst = c2;
            }
        }
        __syncthreads();

        int n = q * blockDim.x + threadIdx.x;
        if (n >= N_NODES) return;
        float a = prelu_a[0];
        float x0 = x[2 * n], x1 = x[2 * n + 1];
        float p = sconst;
#pragma unroll
        for (int k = 0; k < HID; k++) {
            float h1 = fmaf(w1[2 * k], x0, fmaf(w1[2 * k + 1], x1, b1[k]));
            float h  = fmaf(h1, ssc[k], ssh[k]);
            float hp = (h >= 0.f) ? h : a * h;
            p = fmaf(hp, swu[k], p);
        }
        g_p[n] = p;
    }
}

// ---------------------------------------------------------------------------
// K_agg: warp per dst node; dst row preloaded; metadata gathered 32-wide;
// row loads software-pipelined 2 deep.
// ---------------------------------------------------------------------------
__global__ void k_agg(float* __restrict__ out) {
    int gw   = (blockIdx.x * blockDim.x + threadIdx.x) >> 5;
    int lane = threadIdx.x & 31;
    if (gw >= N_NODES) return;

    int beg = g_rowstart[gw];
    int end = g_rowstart[gw + 1];

    const uint4* bptr = (const uint4*)(g_vh + (size_t)gw * VDIM);
    uint4 d0 = __ldg(bptr + lane);
    uint4 d1 = __ldg(bptr + 32 + lane);

    float acc[16];
#pragma unroll
    for (int j = 0; j < 16; j++) acc[j] = 0.f;

    for (int base = beg; base < end; base += 32) {
        int cnt = min(32, end - base);
        int   src = 0;
        float ps  = 0.f;
        if (lane < cnt) {
            src = __ldg(&g_csr[base + lane]);
            ps  = __ldg(&g_p[src]);
        }
        int   s0 = __shfl_sync(0xffffffffu, src, 0);
        float p0 = __shfl_sync(0xffffffffu, ps, 0);
        const uint4* r0 = (const uint4*)(g_vh + (size_t)s0 * VDIM);
        uint4 a0 = r0[lane];
        uint4 a1 = r0[32 + lane];

        for (int j = 0; j < cnt; j++) {
            uint4 b0, b1;
            float p1 = 0.f;
            if (j + 1 < cnt) {
                int s1 = __shfl_sync(0xffffffffu, src, j + 1);
                p1 = __shfl_sync(0xffffffffu, ps, j + 1);
                const uint4* rn = (const uint4*)(g_vh + (size_t)s1 * VDIM);
                b0 = rn[lane];
                b1 = rn[32 + lane];
            } else {
                b0 = a0; b1 = a1;
            }
            float2 f;
            f = __half22float2(*(__half2*)&a0.x); acc[0]  = fmaf(f.x, p0, acc[0]);  acc[1]  = fmaf(f.y, p0, acc[1]);
            f = __half22float2(*(__half2*)&a0.y); acc[2]  = fmaf(f.x, p0, acc[2]);  acc[3]  = fmaf(f.y, p0, acc[3]);
            f = __half22float2(*(__half2*)&a0.z); acc[4]  = fmaf(f.x, p0, acc[4]);  acc[5]  = fmaf(f.y, p0, acc[5]);
            f = __half22float2(*(__half2*)&a0.w); acc[6]  = fmaf(f.x, p0, acc[6]);  acc[7]  = fmaf(f.y, p0, acc[7]);
            f = __half22float2(*(__half2*)&a1.x); acc[8]  = fmaf(f.x, p0, acc[8]);  acc[9]  = fmaf(f.y, p0, acc[9]);
            f = __half22float2(*(__half2*)&a1.y); acc[10] = fmaf(f.x, p0, acc[10]); acc[11] = fmaf(f.y, p0, acc[11]);
            f = __half22float2(*(__half2*)&a1.z); acc[12] = fmaf(f.x, p0, acc[12]); acc[13] = fmaf(f.y, p0, acc[13]);
            f = __half22float2(*(__half2*)&a1.w); acc[14] = fmaf(f.x, p0, acc[14]); acc[15] = fmaf(f.y, p0, acc[15]);
            a0 = b0; a1 = b1; p0 = p1;
        }
    }

    float s = 0.f;
    float2 f;
    f = __half22float2(*(__half2*)&d0.x); s = fmaf(acc[0],  f.x, s); s = fmaf(acc[1],  f.y, s);
    f = __half22float2(*(__half2*)&d0.y); s = fmaf(acc[2],  f.x, s); s = fmaf(acc[3],  f.y, s);
    f = __half22float2(*(__half2*)&d0.z); s = fmaf(acc[4],  f.x, s); s = fmaf(acc[5],  f.y, s);
    f = __half22float2(*(__half2*)&d0.w); s = fmaf(acc[6],  f.x, s); s = fmaf(acc[7],  f.y, s);
    f = __half22float2(*(__half2*)&d1.x); s = fmaf(acc[8],  f.x, s); s = fmaf(acc[9],  f.y, s);
    f = __half22float2(*(__half2*)&d1.y); s = fmaf(acc[10], f.x, s); s = fmaf(acc[11], f.y, s);
    f = __half22float2(*(__half2*)&d1.z); s = fmaf(acc[12], f.x, s); s = fmaf(acc[13], f.y, s);
    f = __half22float2(*(__half2*)&d1.w); s = fmaf(acc[14], f.x, s); s = fmaf(acc[15], f.y, s);

#pragma unroll
    for (int off = 16; off > 0; off >>= 1) s += __shfl_xor_sync(0xffffffffu, s, off);

    if (lane == 0) {
        float deg = (float)(end - beg);
        out[gw] = s / fmaxf(deg, 1.0f) + g_c;
    }
}

// ---------------------------------------------------------------------------
extern "C" void kernel_launch(void* const* d_in, const int* in_sizes, int n_in,
                              void* d_out, int out_size) {
    const float* x       = (const float*)d_in[0];
    const float* visual  = (const float*)d_in[1];
    const int*   ei      = (const int*)d_in[2];
    const float* w1      = (const float*)d_in[3];
    const float* b1      = (const float*)d_in[4];
    const float* gamma   = (const float*)d_in[5];
    const float* beta    = (const float*)d_in[6];
    const float* prelu_a = (const float*)d_in[7];
    const float* w2      = (const float*)d_in[8];
    const float* b2      = (const float*)d_in[9];
    const float* wc      = (const float*)d_in[10];
    const float* bc      = (const float*)d_in[11];
    const float* wp      = (const float*)d_in[12];
    const float* bp      = (const float*)d_in[13];
    float*       out     = (float*)d_out;

    k_zero<<<128, 256>>>();
    k_A<<<KA_GRID, 256>>>(visual, ei, x, w1, b1);
    k_scanprep<<<NBLKS + 1, SCAN_BLK>>>(gamma, beta, wc, bc, wp, bp);
    k_B<<<KB_GRID, 256>>>(ei, x, w1, b1, prelu_a, w2, b2);
    k_agg<<<(N_NODES * 32 + 255) / 256, 256>>>(out);
}